// round 14
// baseline (speedup 1.0000x reference)
#include <cuda_runtime.h>
#include <cuda_fp16.h>
#include <cstdint>

#define MDIM 16384
#define NDIM 4096
#define KDIM 4096
#define BM 64
#define BN 128
#define BK 32
#define NKT (KDIM / BK)             // 128
#define A_BYTES (BM * 64)           // 4096
#define B_BYTES (BN * 64)           // 8192
#define STAGE_BYTES (A_BYTES + B_BYTES)   // 12288
#define SMEM_BYTES (3 * STAGE_BYTES)      // 36864 (x2 CTAs = 72KB/SM)
#define NTHR 256

// fp16 operands, word-transposed within each 64-byte (32-col) block:
//   new_word[(o&3)*4 + (o>>2)] = old_word[o]
// so mma-thread t's four needed words are one LDS.128 per row per block.
__device__ __half g_xh[(size_t)MDIM * KDIM];
__device__ __half g_wh[(size_t)NDIM * KDIM];

// ---------------- helpers ----------------
__device__ __forceinline__ uint32_t smem_u32(const void* p) {
    uint32_t a;
    asm("{ .reg .u64 t; cvta.to.shared.u64 t, %1; cvt.u32.u64 %0, t; }" : "=r"(a) : "l"(p));
    return a;
}
__device__ __forceinline__ void cp_async16(uint32_t saddr, const void* gptr) {
    asm volatile("cp.async.cg.shared.global [%0], [%1], 16;"
                 :: "r"(saddr), "l"(__cvta_generic_to_global(gptr)) : "memory");
}
#define CP_COMMIT() asm volatile("cp.async.commit_group;" ::: "memory")
#define CP_WAIT1()  asm volatile("cp.async.wait_group 1;" ::: "memory")
#define CP_WAIT0()  asm volatile("cp.async.wait_group 0;" ::: "memory")

__device__ __forceinline__ uint4 lds128(uint32_t addr) {
    uint4 v;
    asm volatile("ld.shared.v4.b32 {%0,%1,%2,%3}, [%4];"
                 : "=r"(v.x), "=r"(v.y), "=r"(v.z), "=r"(v.w) : "r"(addr));
    return v;
}
__device__ __forceinline__ void hmma(float c[4], uint32_t a0, uint32_t a1,
                                     uint32_t a2, uint32_t a3,
                                     uint32_t b0, uint32_t b1) {
    asm volatile(
        "mma.sync.aligned.m16n8k16.row.col.f32.f16.f16.f32 "
        "{%0,%1,%2,%3}, {%4,%5,%6,%7}, {%8,%9}, {%0,%1,%2,%3};"
        : "+f"(c[0]), "+f"(c[1]), "+f"(c[2]), "+f"(c[3])
        : "r"(a0), "r"(a1), "r"(a2), "r"(a3), "r"(b0), "r"(b1));
}
// transposed word position within a 64B block
__device__ __forceinline__ int tpos(int o) { return ((o & 3) << 2) | (o >> 2); }

// convert 4 consecutive fp32 cols (col0 % 4 == 0) and store word-transposed
__device__ __forceinline__ void cvt_store4(__half* dst, size_t row, int col0, float4 v) {
    __half2 h0 = __floats2half2_rn(v.x, v.y);
    __half2 h1 = __floats2half2_rn(v.z, v.w);
    char* bb = (char*)dst + row * (KDIM * 2) + (col0 >> 5) * 64;
    int W = (col0 >> 1) & 15;
    *(uint32_t*)(bb + tpos(W) * 4)     = *(uint32_t*)&h0;
    *(uint32_t*)(bb + tpos(W + 1) * 4) = *(uint32_t*)&h1;
}

// ---------------- merged prep: LoRA fold + fp16 permute both operands ------
__global__ void prep_kernel(const float* __restrict__ x, const float* __restrict__ w,
                            const float* __restrict__ lA, const float* __restrict__ lB) {
    int tid = threadIdx.x;
    if (blockIdx.x < NDIM) {
        int o = blockIdx.x;
        float bv[16];
#pragma unroll
        for (int r = 0; r < 16; r++) bv[r] = lB[o * 16 + r] * 2.0f;
        const float4* wr = (const float4*)(w + (size_t)o * KDIM);
#pragma unroll 4
        for (int i = 0; i < 4; i++) {
            int j = tid + 256 * i;
            float4 acc = wr[j];
#pragma unroll
            for (int r = 0; r < 16; r++) {
                float4 a = ((const float4*)(lA + (size_t)r * KDIM))[j];
                acc.x += bv[r] * a.x; acc.y += bv[r] * a.y;
                acc.z += bv[r] * a.z; acc.w += bv[r] * a.w;
            }
            cvt_store4(g_wh, o, j * 4, acc);
        }
    } else {
        size_t n4 = (size_t)MDIM * KDIM / 4;
        size_t nblk = (size_t)gridDim.x - NDIM;
        size_t stride = nblk * blockDim.x;
        const float4* in = (const float4*)x;
        for (size_t i = (blockIdx.x - NDIM) * (size_t)blockDim.x + tid; i < n4; i += stride) {
            float4 v = in[i];
            cvt_store4(g_xh, i >> 10, ((int)i & 1023) * 4, v);
        }
    }
}

// --- main GEMM: fp16 m16n8k16, BM=64 BN=128 BK=32, 256 thr, 2 CTAs/SM ---
__global__ __launch_bounds__(NTHR, 2)
void lora_gemm_kernel(const float* __restrict__ bias, float* __restrict__ out) {
    extern __shared__ char smem[];
    const int tid = threadIdx.x;
    const int wid = tid >> 5, lane = tid & 31;
    const int wm = wid >> 2, wn = wid & 3;            // 2 x 4 warps, tile 32x32
    const int m0 = blockIdx.y * BM, n0 = blockIdx.x * BN;
    const uint32_t sbase = smem_u32(smem);

    // per-thread producer pointers (advance +64 B per k-tile)
    const int prow = tid >> 2, pq = tid & 3;          // prow 0..63
    const char* pA  = (const char*)g_xh + (size_t)(m0 + prow) * (KDIM * 2) + pq * 16;
    const char* pB0 = (const char*)g_wh + (size_t)(n0 + prow) * (KDIM * 2) + pq * 16;
    const char* pB1 = pB0 + (size_t)64 * (KDIM * 2);
    const uint32_t dA = tid * 16;                      // A plane dst (4KB)
    const uint32_t dB = A_BYTES + tid * 16;            // B plane dst (first 4KB)

#define ISSUE(S)                                                   \
    do {                                                           \
        cp_async16(sbase + (S) * STAGE_BYTES + dA, pA);            \
        cp_async16(sbase + (S) * STAGE_BYTES + dB, pB0);           \
        cp_async16(sbase + (S) * STAGE_BYTES + dB + 4096, pB1);    \
        pA += 64; pB0 += 64; pB1 += 64;                            \
        CP_COMMIT();                                               \
    } while (0)

    float acc[2][4][4];
#pragma unroll
    for (int ma = 0; ma < 2; ma++)
#pragma unroll
        for (int na = 0; na < 4; na++)
#pragma unroll
            for (int j = 0; j < 4; j++) acc[ma][na][j] = 0.0f;

    ISSUE(0);
    ISSUE(1);

    const int g = lane >> 2, t = lane & 3;
    const uint32_t aoff = (wm * 32 + g) * 64 + t * 16;
    const uint32_t boff = A_BYTES + (wn * 32 + g) * 64 + t * 16;

#define STEP(S, PF)                                                            \
    do {                                                                       \
        if (PF) { CP_WAIT1(); } else { CP_WAIT0(); }                           \
        __syncthreads();                                                       \
        if (PF) ISSUE(((S) + 2) % 3);                                          \
        const uint32_t pa = sbase + (S) * STAGE_BYTES + aoff;                  \
        const uint32_t pb = sbase + (S) * STAGE_BYTES + boff;                  \
        uint4 u[2], v[2], w[4];                                                \
        _Pragma("unroll")                                                      \
        for (int ma = 0; ma < 2; ma++) {                                       \
            u[ma] = lds128(pa + ma * (16 * 64));                               \
            v[ma] = lds128(pa + ma * (16 * 64) + 8 * 64);                      \
        }                                                                      \
        _Pragma("unroll")                                                      \
        for (int na = 0; na < 4; na++)                                         \
            w[na] = lds128(pb + na * (8 * 64));                                \
        _Pragma("unroll")                                                      \
        for (int ma = 0; ma < 2; ma++)                                         \
            _Pragma("unroll")                                                  \
            for (int na = 0; na < 4; na++)                                     \
                hmma(acc[ma][na], u[ma].x, v[ma].x, u[ma].y, v[ma].y,          \
                     w[na].x, w[na].y);                                        \
        _Pragma("unroll")                                                      \
        for (int ma = 0; ma < 2; ma++)                                         \
            _Pragma("unroll")                                                  \
            for (int na = 0; na < 4; na++)                                     \
                hmma(acc[ma][na], u[ma].z, v[ma].z, u[ma].w, v[ma].w,          \
                     w[na].z, w[na].w);                                        \
    } while (0)

    // kt 0..125 (42 x 3, stages compile-time), then 126 (s0), 127 (s1)
    for (int i = 0; i < 42; ++i) {
        STEP(0, 1);
        STEP(1, 1);
        STEP(2, 1);
    }
    STEP(0, 0);
    STEP(1, 0);

#undef STEP
#undef ISSUE

    // epilogue: fused bias + coalesced float2 stores
    const int r0 = m0 + wm * 32 + g;
    const int cbase = n0 + wn * 32 + t * 2;
    float2 bv[4];
#pragma unroll
    for (int na = 0; na < 4; na++)
        bv[na] = *(const float2*)(bias + cbase + na * 8);
#pragma unroll
    for (int ma = 0; ma < 2; ma++) {
        size_t row = (size_t)(r0 + ma * 16);
#pragma unroll
        for (int na = 0; na < 4; na++) {
            float2 v0 = make_float2(acc[ma][na][0] + bv[na].x, acc[ma][na][1] + bv[na].y);
            float2 v1 = make_float2(acc[ma][na][2] + bv[na].x, acc[ma][na][3] + bv[na].y);
            *(float2*)(out + row * NDIM + cbase + na * 8) = v0;
            *(float2*)(out + (row + 8) * NDIM + cbase + na * 8) = v1;
        }
    }
}

// ---------------- launch ----------------
extern "C" void kernel_launch(void* const* d_in, const int* in_sizes, int n_in,
                              void* d_out, int out_size) {
    const float* x      = (const float*)d_in[0];
    const float* weight = (const float*)d_in[1];
    const float* bias   = (const float*)d_in[2];
    const float* lora_A = (const float*)d_in[3];
    const float* lora_B = (const float*)d_in[4];
    float* out = (float*)d_out;

    cudaFuncSetAttribute(lora_gemm_kernel, cudaFuncAttributeMaxDynamicSharedMemorySize,
                         SMEM_BYTES);

    prep_kernel<<<NDIM + 8192, 256>>>(x, weight, lora_A, lora_B);
    dim3 grid(NDIM / BN, MDIM / BM);   // n fastest: x panel stays L2-resident
    lora_gemm_kernel<<<grid, NTHR, SMEM_BYTES>>>(bias, out);
}

// round 15
// speedup vs baseline: 1.1832x; 1.1832x over previous
#include <cuda_runtime.h>
#include <cuda_fp16.h>
#include <cstdint>

#define MDIM 16384
#define NDIM 4096
#define KDIM 4096
#define BM 128
#define BN 256
#define BK 32
#define NKT (KDIM / BK)             // 128
#define A_BYTES (BM * 64)           // 8192
#define B_BYTES (BN * 64)           // 16384
#define STAGE_BYTES (A_BYTES + B_BYTES)   // 24576
#define SMEM_BYTES (3 * STAGE_BYTES)      // 73728
#define NTHR 512

// g_xh: A in fragment-quad order. Per 16-row x 32-col block (1024B):
//   quad qi = g*8 + ((kg*4+t) ^ ((g&1)*4)), 16B = [A[g][kp], A[g+8][kp],
//   A[g][kp+4], A[g+8][kp+4]] with kp = kg*8+t. Blocks laid out
//   [row_block][ktile] so a k-slab is 1024 contiguous bytes.
// g_wh: word-transposed 64B blocks (new_word[(o&3)*4+(o>>2)] = old_word[o]).
__device__ __half g_xh[(size_t)MDIM * KDIM];
__device__ __half g_wh[(size_t)NDIM * KDIM];

// ---------------- helpers ----------------
__device__ __forceinline__ uint32_t smem_u32(const void* p) {
    uint32_t a;
    asm("{ .reg .u64 t; cvta.to.shared.u64 t, %1; cvt.u32.u64 %0, t; }" : "=r"(a) : "l"(p));
    return a;
}
__device__ __forceinline__ void cp_async16(uint32_t saddr, const void* gptr) {
    asm volatile("cp.async.cg.shared.global [%0], [%1], 16;"
                 :: "r"(saddr), "l"(__cvta_generic_to_global(gptr)) : "memory");
}
#define CP_COMMIT() asm volatile("cp.async.commit_group;" ::: "memory")
#define CP_WAIT1()  asm volatile("cp.async.wait_group 1;" ::: "memory")
#define CP_WAIT0()  asm volatile("cp.async.wait_group 0;" ::: "memory")

__device__ __forceinline__ uint4 lds128(uint32_t addr) {
    uint4 v;
    asm volatile("ld.shared.v4.b32 {%0,%1,%2,%3}, [%4];"
                 : "=r"(v.x), "=r"(v.y), "=r"(v.z), "=r"(v.w) : "r"(addr));
    return v;
}
__device__ __forceinline__ void hmma(float c[4], uint32_t a0, uint32_t a1,
                                     uint32_t a2, uint32_t a3,
                                     uint32_t b0, uint32_t b1) {
    asm volatile(
        "mma.sync.aligned.m16n8k16.row.col.f32.f16.f16.f32 "
        "{%0,%1,%2,%3}, {%4,%5,%6,%7}, {%8,%9}, {%0,%1,%2,%3};"
        : "+f"(c[0]), "+f"(c[1]), "+f"(c[2]), "+f"(c[3])
        : "r"(a0), "r"(a1), "r"(a2), "r"(a3), "r"(b0), "r"(b1));
}
// transposed word position within a 64B block (B layout)
__device__ __forceinline__ int tpos(int o) { return ((o & 3) << 2) | (o >> 2); }

// store one half2 word of x into the fragment-quad A layout
__device__ __forceinline__ void store_xword(size_t r, int c, uint32_t wv) {
    int kt = c >> 5, kp = (c & 31) >> 1;
    int kg = kp >> 3, t = kp & 3, half = (kp >> 2) & 1;
    int g = (int)(r & 7), hi = (int)((r >> 3) & 1);
    int qi = g * 8 + (((kg << 2) | t) ^ ((g & 1) << 2));
    size_t byte = (((r >> 4) * NKT + kt) << 10) + qi * 16 + (((half << 1) | hi) << 2);
    *(uint32_t*)((char*)g_xh + byte) = wv;
}

// convert 4 consecutive fp32 cols (col0 % 4 == 0) and store word-transposed (W)
__device__ __forceinline__ void cvt_store4_w(__half* dst, size_t row, int col0, float4 v) {
    __half2 h0 = __floats2half2_rn(v.x, v.y);
    __half2 h1 = __floats2half2_rn(v.z, v.w);
    char* bb = (char*)dst + row * (KDIM * 2) + (col0 >> 5) * 64;
    int W = (col0 >> 1) & 15;
    *(uint32_t*)(bb + tpos(W) * 4)     = *(uint32_t*)&h0;
    *(uint32_t*)(bb + tpos(W + 1) * 4) = *(uint32_t*)&h1;
}

// ---------------- merged prep: LoRA fold + both permuted layouts ------
__global__ void prep_kernel(const float* __restrict__ x, const float* __restrict__ w,
                            const float* __restrict__ lA, const float* __restrict__ lB) {
    int tid = threadIdx.x;
    if (blockIdx.x < NDIM) {
        int o = blockIdx.x;
        float bv[16];
#pragma unroll
        for (int r = 0; r < 16; r++) bv[r] = lB[o * 16 + r] * 2.0f;
        const float4* wr = (const float4*)(w + (size_t)o * KDIM);
#pragma unroll 4
        for (int i = 0; i < 4; i++) {
            int j = tid + 256 * i;
            float4 acc = wr[j];
#pragma unroll
            for (int r = 0; r < 16; r++) {
                float4 a = ((const float4*)(lA + (size_t)r * KDIM))[j];
                acc.x += bv[r] * a.x; acc.y += bv[r] * a.y;
                acc.z += bv[r] * a.z; acc.w += bv[r] * a.w;
            }
            cvt_store4_w(g_wh, o, j * 4, acc);
        }
    } else {
        size_t n4 = (size_t)MDIM * KDIM / 4;
        size_t nblk = (size_t)gridDim.x - NDIM;
        size_t stride = nblk * blockDim.x;
        const float4* in = (const float4*)x;
        for (size_t i = (blockIdx.x - NDIM) * (size_t)blockDim.x + tid; i < n4; i += stride) {
            float4 v = in[i];
            size_t r = i >> 10;
            int c0 = ((int)i & 1023) * 4;
            __half2 h0 = __floats2half2_rn(v.x, v.y);
            __half2 h1 = __floats2half2_rn(v.z, v.w);
            store_xword(r, c0,     *(uint32_t*)&h0);
            store_xword(r, c0 + 2, *(uint32_t*)&h1);
        }
    }
}

// --- main GEMM: fp16 m16n8k16, BM=128 BN=256 BK=32, 512 thr, quad-A ---
__global__ __launch_bounds__(NTHR, 1)
void lora_gemm_kernel(const float* __restrict__ bias, float* __restrict__ out) {
    extern __shared__ char smem[];
    const int tid = threadIdx.x;
    const int wid = tid >> 5, lane = tid & 31;
    const int wm = wid >> 2, wn = wid & 3;            // 4 x 4 warps, tile 32x64
    const int m0 = blockIdx.y * BM, n0 = blockIdx.x * BN;
    const uint32_t sbase = smem_u32(smem);

    // producers: A one chunk/thread (quad-block layout, +1024/kt), B two (+64/kt)
    const char* pA = (const char*)g_xh +
        ((size_t)((m0 >> 4) + (tid >> 6)) * NKT) * 1024 + (tid & 63) * 16;
    const int prow = tid >> 2, pq = tid & 3;
    const char* pB0 = (const char*)g_wh + (size_t)(n0 + prow) * (KDIM * 2) + pq * 16;
    const char* pB1 = pB0 + (size_t)128 * (KDIM * 2);
    const uint32_t dA = tid * 16;
    const uint32_t dB = A_BYTES + tid * 16;

#define ISSUE(S)                                                   \
    do {                                                           \
        cp_async16(sbase + (S) * STAGE_BYTES + dA, pA);            \
        cp_async16(sbase + (S) * STAGE_BYTES + dB, pB0);           \
        cp_async16(sbase + (S) * STAGE_BYTES + dB + 8192, pB1);    \
        pA += 1024; pB0 += 64; pB1 += 64;                          \
        CP_COMMIT();                                               \
    } while (0)

    float acc[2][8][4];
#pragma unroll
    for (int ma = 0; ma < 2; ma++)
#pragma unroll
        for (int na = 0; na < 8; na++)
#pragma unroll
            for (int j = 0; j < 4; j++) acc[ma][na][j] = 0.0f;

    ISSUE(0);
    ISSUE(1);

    const int g = lane >> 2, t = lane & 3;
    // A quad offsets for kg0/kg1 (16B-swizzled, conflict-free per quarter-warp)
    const int qi0 = g * 8 + (t ^ ((g & 1) << 2));
    const int qi1 = g * 8 + ((4 | t) ^ ((g & 1) << 2));
    const uint32_t a00 = (wm * 2) * 1024 + qi0 * 16;      // ma=0, kg0
    const uint32_t a01 = (wm * 2) * 1024 + qi1 * 16;      // ma=0, kg1
    const uint32_t boff = A_BYTES + (wn * 64 + g) * 64 + t * 16;

#define STEP(S, PF)                                                            \
    do {                                                                       \
        if (PF) { CP_WAIT1(); } else { CP_WAIT0(); }                           \
        __syncthreads();                                                       \
        if (PF) ISSUE(((S) + 2) % 3);                                          \
        const uint32_t stg = sbase + (S) * STAGE_BYTES;                        \
        const uint32_t pb = stg + boff;                                        \
        uint4 q0[2], q1[2], w[8];                                              \
        _Pragma("unroll")                                                      \
        for (int ma = 0; ma < 2; ma++) {                                       \
            q0[ma] = lds128(stg + a00 + ma * 1024);                            \
            q1[ma] = lds128(stg + a01 + ma * 1024);                            \
        }                                                                      \
        _Pragma("unroll")                                                      \
        for (int na = 0; na < 8; na++)                                         \
            w[na] = lds128(pb + na * (8 * 64));                                \
        _Pragma("unroll")                                                      \
        for (int ma = 0; ma < 2; ma++)                                         \
            _Pragma("unroll")                                                  \
            for (int na = 0; na < 8; na++)                                     \
                hmma(acc[ma][na], q0[ma].x, q0[ma].y, q0[ma].z, q0[ma].w,      \
                     w[na].x, w[na].y);                                        \
        _Pragma("unroll")                                                      \
        for (int ma = 0; ma < 2; ma++)                                         \
            _Pragma("unroll")                                                  \
            for (int na = 0; na < 8; na++)                                     \
                hmma(acc[ma][na], q1[ma].x, q1[ma].y, q1[ma].z, q1[ma].w,      \
                     w[na].z, w[na].w);                                        \
    } while (0)

    // kt 0..125 (42 x 3, stages compile-time), then 126 (s0), 127 (s1)
    for (int i = 0; i < 42; ++i) {
        STEP(0, 1);
        STEP(1, 1);
        STEP(2, 1);
    }
    STEP(0, 0);
    STEP(1, 0);

#undef STEP
#undef ISSUE

    // epilogue: fused bias + coalesced float2 stores
    const int r0 = m0 + wm * 32 + g;
    const int cbase = n0 + wn * 64 + t * 2;
    float2 bv[8];
#pragma unroll
    for (int na = 0; na < 8; na++)
        bv[na] = *(const float2*)(bias + cbase + na * 8);
#pragma unroll
    for (int ma = 0; ma < 2; ma++) {
        size_t row = (size_t)(r0 + ma * 16);
#pragma unroll
        for (int na = 0; na < 8; na++) {
            float2 v0 = make_float2(acc[ma][na][0] + bv[na].x, acc[ma][na][1] + bv[na].y);
            float2 v1 = make_float2(acc[ma][na][2] + bv[na].x, acc[ma][na][3] + bv[na].y);
            *(float2*)(out + row * NDIM + cbase + na * 8) = v0;
            *(float2*)(out + (row + 8) * NDIM + cbase + na * 8) = v1;
        }
    }
}

// ---------------- launch ----------------
extern "C" void kernel_launch(void* const* d_in, const int* in_sizes, int n_in,
                              void* d_out, int out_size) {
    const float* x      = (const float*)d_in[0];
    const float* weight = (const float*)d_in[1];
    const float* bias   = (const float*)d_in[2];
    const float* lora_A = (const float*)d_in[3];
    const float* lora_B = (const float*)d_in[4];
    float* out = (float*)d_out;

    cudaFuncSetAttribute(lora_gemm_kernel, cudaFuncAttributeMaxDynamicSharedMemorySize,
                         SMEM_BYTES);

    prep_kernel<<<NDIM + 8192, 256>>>(x, weight, lora_A, lora_B);
    dim3 grid(NDIM / BN, MDIM / BM);   // n fastest: x panel stays L2-resident
    lora_gemm_kernel<<<grid, NTHR, SMEM_BYTES>>>(bias, out);
}

// round 16
// speedup vs baseline: 1.4003x; 1.1835x over previous
#include <cuda_runtime.h>
#include <cuda_fp16.h>
#include <cstdint>

#define MDIM 16384
#define NDIM 4096
#define KDIM 4096
#define BM 128
#define BN 128
#define BK 32
#define NKT (KDIM / BK)             // 128
#define A_BYTES (BM * 64)           // 8192
#define B_BYTES (BN * 64)           // 8192
#define STAGE_BYTES (A_BYTES + B_BYTES)   // 16384
#define SMEM_BYTES (3 * STAGE_BYTES)      // 49152 (x2 CTAs = 96KB/SM)
#define NTHR 256

// g_xh: A in fragment-quad order. Per 16-row x 32-col block (1024B):
//   quad qi = g*8 + ((kg*4+t) ^ ((g&1)*4)), 16B = [A[g][kp], A[g+8][kp],
//   A[g][kp+4], A[g+8][kp+4]] with kp = kg*8+t. Blocks laid out
//   [row_block][ktile] so a k-slab is 1024 contiguous bytes.
// g_wh: word-transposed 64B blocks (new_word[(o&3)*4+(o>>2)] = old_word[o]).
__device__ __half g_xh[(size_t)MDIM * KDIM];
__device__ __half g_wh[(size_t)NDIM * KDIM];

// ---------------- helpers ----------------
__device__ __forceinline__ uint32_t smem_u32(const void* p) {
    uint32_t a;
    asm("{ .reg .u64 t; cvta.to.shared.u64 t, %1; cvt.u32.u64 %0, t; }" : "=r"(a) : "l"(p));
    return a;
}
__device__ __forceinline__ void cp_async16(uint32_t saddr, const void* gptr) {
    asm volatile("cp.async.cg.shared.global [%0], [%1], 16;"
                 :: "r"(saddr), "l"(__cvta_generic_to_global(gptr)) : "memory");
}
#define CP_COMMIT() asm volatile("cp.async.commit_group;" ::: "memory")
#define CP_WAIT1()  asm volatile("cp.async.wait_group 1;" ::: "memory")
#define CP_WAIT0()  asm volatile("cp.async.wait_group 0;" ::: "memory")

__device__ __forceinline__ uint4 lds128(uint32_t addr) {
    uint4 v;
    asm volatile("ld.shared.v4.b32 {%0,%1,%2,%3}, [%4];"
                 : "=r"(v.x), "=r"(v.y), "=r"(v.z), "=r"(v.w) : "r"(addr));
    return v;
}
__device__ __forceinline__ void hmma(float c[4], uint32_t a0, uint32_t a1,
                                     uint32_t a2, uint32_t a3,
                                     uint32_t b0, uint32_t b1) {
    asm volatile(
        "mma.sync.aligned.m16n8k16.row.col.f32.f16.f16.f32 "
        "{%0,%1,%2,%3}, {%4,%5,%6,%7}, {%8,%9}, {%0,%1,%2,%3};"
        : "+f"(c[0]), "+f"(c[1]), "+f"(c[2]), "+f"(c[3])
        : "r"(a0), "r"(a1), "r"(a2), "r"(a3), "r"(b0), "r"(b1));
}
// transposed word position within a 64B block (B layout)
__device__ __forceinline__ int tpos(int o) { return ((o & 3) << 2) | (o >> 2); }

// store one half2 word of x into the fragment-quad A layout
__device__ __forceinline__ void store_xword(size_t r, int c, uint32_t wv) {
    int kt = c >> 5, kp = (c & 31) >> 1;
    int kg = kp >> 3, t = kp & 3, half = (kp >> 2) & 1;
    int g = (int)(r & 7), hi = (int)((r >> 3) & 1);
    int qi = g * 8 + (((kg << 2) | t) ^ ((g & 1) << 2));
    size_t byte = (((r >> 4) * NKT + kt) << 10) + qi * 16 + (((half << 1) | hi) << 2);
    *(uint32_t*)((char*)g_xh + byte) = wv;
}

// convert 4 consecutive fp32 cols (col0 % 4 == 0) and store word-transposed (W)
__device__ __forceinline__ void cvt_store4_w(__half* dst, size_t row, int col0, float4 v) {
    __half2 h0 = __floats2half2_rn(v.x, v.y);
    __half2 h1 = __floats2half2_rn(v.z, v.w);
    char* bb = (char*)dst + row * (KDIM * 2) + (col0 >> 5) * 64;
    int W = (col0 >> 1) & 15;
    *(uint32_t*)(bb + tpos(W) * 4)     = *(uint32_t*)&h0;
    *(uint32_t*)(bb + tpos(W + 1) * 4) = *(uint32_t*)&h1;
}

// ---------------- merged prep: LoRA fold + both permuted layouts ------
__global__ void prep_kernel(const float* __restrict__ x, const float* __restrict__ w,
                            const float* __restrict__ lA, const float* __restrict__ lB) {
    int tid = threadIdx.x;
    if (blockIdx.x < NDIM) {
        int o = blockIdx.x;
        float bv[16];
#pragma unroll
        for (int r = 0; r < 16; r++) bv[r] = lB[o * 16 + r] * 2.0f;
        const float4* wr = (const float4*)(w + (size_t)o * KDIM);
#pragma unroll 4
        for (int i = 0; i < 4; i++) {
            int j = tid + 256 * i;
            float4 acc = wr[j];
#pragma unroll
            for (int r = 0; r < 16; r++) {
                float4 a = ((const float4*)(lA + (size_t)r * KDIM))[j];
                acc.x += bv[r] * a.x; acc.y += bv[r] * a.y;
                acc.z += bv[r] * a.z; acc.w += bv[r] * a.w;
            }
            cvt_store4_w(g_wh, o, j * 4, acc);
        }
    } else {
        size_t n4 = (size_t)MDIM * KDIM / 4;
        size_t nblk = (size_t)gridDim.x - NDIM;
        size_t stride = nblk * blockDim.x;
        const float4* in = (const float4*)x;
        for (size_t i = (blockIdx.x - NDIM) * (size_t)blockDim.x + tid; i < n4; i += stride) {
            float4 v = in[i];
            size_t r = i >> 10;
            int c0 = ((int)i & 1023) * 4;
            __half2 h0 = __floats2half2_rn(v.x, v.y);
            __half2 h1 = __floats2half2_rn(v.z, v.w);
            store_xword(r, c0,     *(uint32_t*)&h0);
            store_xword(r, c0 + 2, *(uint32_t*)&h1);
        }
    }
}

// --- main GEMM: fp16 m16n8k16, BM=BN=128, 256 thr, 2 CTAs/SM, quad-A ---
__global__ __launch_bounds__(NTHR, 2)
void lora_gemm_kernel(const float* __restrict__ bias, float* __restrict__ out) {
    extern __shared__ char smem[];
    const int tid = threadIdx.x;
    const int wid = tid >> 5, lane = tid & 31;
    const int wm = wid >> 2, wn = wid & 3;            // 2 x 4 warps, tile 64x32
    const int m0 = blockIdx.y * BM, n0 = blockIdx.x * BN;
    const uint32_t sbase = smem_u32(smem);

    // producers: A two chunks/thread (quad layout, +1024/kt), B two (+64/kt)
    const char* pA0 = (const char*)g_xh +
        ((size_t)((m0 >> 4) + (tid >> 6)) * NKT) * 1024 + (tid & 63) * 16;
    const char* pA1 = (const char*)g_xh +
        ((size_t)((m0 >> 4) + ((tid + 256) >> 6)) * NKT) * 1024 + (tid & 63) * 16;
    const int prow = tid >> 2, pq = tid & 3;
    const char* pB0 = (const char*)g_wh + (size_t)(n0 + prow) * (KDIM * 2) + pq * 16;
    const char* pB1 = pB0 + (size_t)64 * (KDIM * 2);
    const uint32_t dA = tid * 16;
    const uint32_t dB = A_BYTES + tid * 16;

#define ISSUE(S)                                                   \
    do {                                                           \
        cp_async16(sbase + (S) * STAGE_BYTES + dA, pA0);           \
        cp_async16(sbase + (S) * STAGE_BYTES + dA + 4096, pA1);    \
        cp_async16(sbase + (S) * STAGE_BYTES + dB, pB0);           \
        cp_async16(sbase + (S) * STAGE_BYTES + dB + 4096, pB1);    \
        pA0 += 1024; pA1 += 1024; pB0 += 64; pB1 += 64;            \
        CP_COMMIT();                                               \
    } while (0)

    float acc[4][4][4];
#pragma unroll
    for (int ma = 0; ma < 4; ma++)
#pragma unroll
        for (int na = 0; na < 4; na++)
#pragma unroll
            for (int j = 0; j < 4; j++) acc[ma][na][j] = 0.0f;

    ISSUE(0);
    ISSUE(1);

    const int g = lane >> 2, t = lane & 3;
    // A quad offsets for kg0/kg1 (16B-swizzled, conflict-free per quarter-warp)
    const int qi0 = g * 8 + (t ^ ((g & 1) << 2));
    const int qi1 = g * 8 + ((4 | t) ^ ((g & 1) << 2));
    const uint32_t a00 = (wm * 4) * 1024 + qi0 * 16;      // ma=0, kg0
    const uint32_t a01 = (wm * 4) * 1024 + qi1 * 16;      // ma=0, kg1
    const uint32_t boff = A_BYTES + (wn * 32 + g) * 64 + t * 16;

#define STEP(S, PF)                                                            \
    do {                                                                       \
        if (PF) { CP_WAIT1(); } else { CP_WAIT0(); }                           \
        __syncthreads();                                                       \
        if (PF) ISSUE(((S) + 2) % 3);                                          \
        const uint32_t stg = sbase + (S) * STAGE_BYTES;                        \
        const uint32_t pb = stg + boff;                                        \
        uint4 w[4], q[4];                                                      \
        _Pragma("unroll")                                                      \
        for (int na = 0; na < 4; na++)                                         \
            w[na] = lds128(pb + na * (8 * 64));                                \
        _Pragma("unroll")                                                      \
        for (int ma = 0; ma < 4; ma++)                                         \
            q[ma] = lds128(stg + a00 + ma * 1024);                             \
        _Pragma("unroll")                                                      \
        for (int ma = 0; ma < 4; ma++)                                         \
            _Pragma("unroll")                                                  \
            for (int na = 0; na < 4; na++)                                     \
                hmma(acc[ma][na], q[ma].x, q[ma].y, q[ma].z, q[ma].w,          \
                     w[na].x, w[na].y);                                        \
        _Pragma("unroll")                                                      \
        for (int ma = 0; ma < 4; ma++)                                         \
            q[ma] = lds128(stg + a01 + ma * 1024);                             \
        _Pragma("unroll")                                                      \
        for (int ma = 0; ma < 4; ma++)                                         \
            _Pragma("unroll")                                                  \
            for (int na = 0; na < 4; na++)                                     \
                hmma(acc[ma][na], q[ma].x, q[ma].y, q[ma].z, q[ma].w,          \
                     w[na].z, w[na].w);                                        \
    } while (0)

    // kt 0..125 (42 x 3, stages compile-time), then 126 (s0), 127 (s1)
    for (int i = 0; i < 42; ++i) {
        STEP(0, 1);
        STEP(1, 1);
        STEP(2, 1);
    }
    STEP(0, 0);
    STEP(1, 0);

#undef STEP
#undef ISSUE

    // epilogue: fused bias + coalesced float2 stores
    const int r0 = m0 + wm * 64 + g;
    const int cbase = n0 + wn * 32 + t * 2;
    float2 bv[4];
#pragma unroll
    for (int na = 0; na < 4; na++)
        bv[na] = *(const float2*)(bias + cbase + na * 8);
#pragma unroll
    for (int ma = 0; ma < 4; ma++) {
        size_t row = (size_t)(r0 + ma * 16);
#pragma unroll
        for (int na = 0; na < 4; na++) {
            float2 v0 = make_float2(acc[ma][na][0] + bv[na].x, acc[ma][na][1] + bv[na].y);
            float2 v1 = make_float2(acc[ma][na][2] + bv[na].x, acc[ma][na][3] + bv[na].y);
            *(float2*)(out + row * NDIM + cbase + na * 8) = v0;
            *(float2*)(out + (row + 8) * NDIM + cbase + na * 8) = v1;
        }
    }
}

// ---------------- launch ----------------
extern "C" void kernel_launch(void* const* d_in, const int* in_sizes, int n_in,
                              void* d_out, int out_size) {
    const float* x      = (const float*)d_in[0];
    const float* weight = (const float*)d_in[1];
    const float* bias   = (const float*)d_in[2];
    const float* lora_A = (const float*)d_in[3];
    const float* lora_B = (const float*)d_in[4];
    float* out = (float*)d_out;

    cudaFuncSetAttribute(lora_gemm_kernel, cudaFuncAttributeMaxDynamicSharedMemorySize,
                         SMEM_BYTES);

    prep_kernel<<<NDIM + 8192, 256>>>(x, weight, lora_A, lora_B);
    dim3 grid(NDIM / BN, MDIM / BM);   // n fastest: x panel stays L2-resident
    lora_gemm_kernel<<<grid, NTHR, SMEM_BYTES>>>(bias, out);
}